// round 2
// baseline (speedup 1.0000x reference)
#include <cuda_runtime.h>

// Problem constants: query [32, 2048] f32, W [2048, 100] f32, out [32, 100] f32.
// out[b,o] = sum_j (q[b,j] - (2048*trunc(q[b,j]) + S[b]))^2 * W[j,o]
// with S[b] = sum_j trunc(q[b,j]).  All intermediates integer-exact in f32.

#define BATCH     32
#define NDIM      2048
#define NOUT      100
#define NTHREADS  512
#define YSPLIT    4
#define COLS_PER_BLK 25          // NOUT / YSPLIT
#define JPART     (NDIM / 16)    // 128 j's per part (16 parts of the block)

__global__ __launch_bounds__(NTHREADS)
void fused_rem_matvec(const float* __restrict__ q,
                      const float* __restrict__ W,
                      float* __restrict__ out) {
    const int b       = blockIdx.x;
    const int colbase = blockIdx.y * COLS_PER_BLK;
    const float* qb   = q + b * NDIM;

    __shared__ float rem[NDIM];        // 8 KB
    __shared__ int   wsum[16];
    __shared__ float partial[16][32];  // 2 KB

    const int tid = threadIdx.x;

    // ---- Phase 1: c = trunc(q), stash c, block-reduce S ----
    int s = 0;
    #pragma unroll
    for (int j = tid; j < NDIM; j += NTHREADS) {
        float v = qb[j];
        int   c = (int)v;              // trunc toward zero, matches astype(int32)
        s += c;
        rem[j] = (float)c;             // stash c temporarily
    }
    s = __reduce_add_sync(0xffffffffu, s);
    if ((tid & 31) == 0) wsum[tid >> 5] = s;
    __syncthreads();

    int S = 0;
    #pragma unroll
    for (int w = 0; w < 16; w++) S += wsum[w];
    const float Sf = (float)S;

    // ---- Phase 2: rem[j] = (q - (2048*c + S))^2 (each thread rewrites own stash) ----
    #pragma unroll
    for (int j = tid; j < NDIM; j += NTHREADS) {
        float d = qb[j] - fmaf(2048.0f, rem[j], Sf);
        rem[j] = d * d;
    }
    __syncthreads();

    // ---- Phase 3: matvec over 25 W columns. o = tid%32 (coalesced W), part = tid/32 ----
    const int o    = tid & 31;
    const int part = tid >> 5;         // 0..15
    float acc = 0.0f;
    if (o < COLS_PER_BLK) {
        const float* Wp = W + colbase + o;
        const int j0 = part * JPART;
        #pragma unroll 8
        for (int j = j0; j < j0 + JPART; j++)
            acc = fmaf(rem[j], Wp[j * NOUT], acc);
    }
    partial[part][o] = acc;
    __syncthreads();

    if (part == 0 && o < COLS_PER_BLK) {
        float r = 0.0f;
        #pragma unroll
        for (int p = 0; p < 16; p++) r += partial[p][o];
        out[b * NOUT + colbase + o] = r;
    }
}

extern "C" void kernel_launch(void* const* d_in, const int* in_sizes, int n_in,
                              void* d_out, int out_size) {
    const float* q = (const float*)d_in[0];   // [32, 2048]
    const float* W = (const float*)d_in[1];   // [2048, 100]
    float* out = (float*)d_out;               // [32, 100]
    (void)in_sizes; (void)n_in; (void)out_size;

    dim3 grid(BATCH, YSPLIT);
    fused_rem_matvec<<<grid, NTHREADS>>>(q, W, out);
}